// round 4
// baseline (speedup 1.0000x reference)
#include <cuda_runtime.h>

// Problem geometry
#define S      160
#define NB     4
#define SLICE  (S * S)              // 25600
#define S3     (S * S * S)          // 4,096,000
#define NVOX   (NB * S3)            // 16,384,000
#define LROW   (5 * S)              // 800: one (d) row of 5 channels
#define SSIM_C1 0.0001f
#define SSIM_C2 0.0009f

// H-tile for fused W+H kernel
#define TH     15
#define HROWS  (TH + 10)            // 25
#define NTILE  11                   // ceil(160/15)

// Scratch after W+H conv. Layout [n][h][d][c][w]  (c,w innermost -> K3 reads
// one contiguous 3200B chunk per d-step).
__device__ float g_bufB[5 * NVOX];
__device__ double g_sum;

// 11-tap Gaussian, sigma=1.5, normalized.
#define GW_INIT { 0.00102838f, 0.00759875f, 0.03600078f, 0.10936070f, \
                  0.21300554f, 0.26601172f, 0.21300554f, 0.10936070f, \
                  0.03600078f, 0.00759875f, 0.00102838f }

__global__ void k0_init() { g_sum = 0.0; }

// ---------------------------------------------------------------------------
// K12: fused products + W-conv + H-conv for one (n, d, h-tile).
// 256 threads, 112 KB dynamic smem (xs, ys, 5x wb planes).
// W-stage: thread per (row, w) point, computes ALL 5 channels from the same
//          22 smem reads (5x less smem traffic than channel-sequential).
// H-stage: thread per w (160 active), 5-channel register shift window.
// Only 2 __syncthreads total.
// ---------------------------------------------------------------------------
extern __shared__ float s_raw[];

__global__ __launch_bounds__(256, 2) void k12_wh(
    const float* __restrict__ x, const float* __restrict__ y)
{
    const float GW[11] = GW_INIT;
    float* xs = s_raw;                        // [HROWS][S]
    float* ys = xs + HROWS * S;               // [HROWS][S]
    float* wb = ys + HROWS * S;               // [5][HROWS][S]

    const int ht = blockIdx.x;
    const int d  = blockIdx.y;
    const int n  = blockIdx.z;
    const int h0 = ht * TH;
    const int tid = threadIdx.x;
    const size_t sbase = (size_t)n * S3 + (size_t)d * SLICE;

    // Load 25 input rows (zero-padded at volume edges), coalesced.
    for (int i = tid; i < HROWS * S; i += 256) {
        const int r = i / S, w = i - r * S;
        const int hh = h0 - 5 + r;
        float a = 0.f, b = 0.f;
        if (hh >= 0 && hh < S) {
            const size_t g = sbase + (size_t)hh * S + w;
            a = x[g]; b = y[g];
        }
        xs[i] = a; ys[i] = b;
    }
    __syncthreads();

    // ---- W-stage: all 5 channels per point ----
    for (int i = tid; i < HROWS * S; i += 256) {
        const int r = i / S, w = i - r * S;
        float A = 0.f, B = 0.f, AA = 0.f, BB = 0.f, AB = 0.f;
        #pragma unroll
        for (int k = 0; k < 11; ++k) {
            const int ww = w - 5 + k;
            if (ww >= 0 && ww < S) {
                const float a = xs[r * S + ww];
                const float b = ys[r * S + ww];
                const float g = GW[k];
                A  += g * a;
                B  += g * b;
                AA += g * (a * a);
                BB += g * (b * b);
                AB += g * (a * b);
            }
        }
        wb[0 * HROWS * S + i] = A;
        wb[1 * HROWS * S + i] = B;
        wb[2 * HROWS * S + i] = AA;
        wb[3 * HROWS * S + i] = BB;
        wb[4 * HROWS * S + i] = AB;
    }
    __syncthreads();

    // ---- H-stage: conv along h, 5-channel register shift window ----
    if (tid < S) {
        const int w = tid;
        float r0[11], r1[11], r2[11], r3[11], r4[11];
        #pragma unroll
        for (int k = 0; k < 11; ++k) {
            r0[k] = wb[0 * HROWS * S + k * S + w];
            r1[k] = wb[1 * HROWS * S + k * S + w];
            r2[k] = wb[2 * HROWS * S + k * S + w];
            r3[k] = wb[3 * HROWS * S + k * S + w];
            r4[k] = wb[4 * HROWS * S + k * S + w];
        }

        // dst index: (((n*S + h)*S + d)*5 + c)*S + w
        #pragma unroll
        for (int o = 0; o < TH; ++o) {
            const int h = h0 + o;
            if (h < S) {
                float A = 0.f, B = 0.f, AA = 0.f, BB = 0.f, AB = 0.f;
                #pragma unroll
                for (int k = 0; k < 11; ++k) {
                    const float g = GW[k];
                    A  += g * r0[k]; B  += g * r1[k];
                    AA += g * r2[k]; BB += g * r3[k];
                    AB += g * r4[k];
                }
                float* dst = g_bufB
                    + ((size_t)(n * S + h) * S + d) * LROW + w;
                dst[0 * S] = A;
                dst[1 * S] = B;
                dst[2 * S] = AA;
                dst[3 * S] = BB;
                dst[4 * S] = AB;
            }
            #pragma unroll
            for (int k = 0; k < 10; ++k) {
                r0[k] = r0[k+1]; r1[k] = r1[k+1]; r2[k] = r2[k+1];
                r3[k] = r3[k+1]; r4[k] = r4[k+1];
            }
            if (o + 11 < HROWS) {
                const int rr = (o + 11) * S + w;
                r0[10] = wb[0 * HROWS * S + rr];
                r1[10] = wb[1 * HROWS * S + rr];
                r2[10] = wb[2 * HROWS * S + rr];
                r3[10] = wb[3 * HROWS * S + rr];
                r4[10] = wb[4 * HROWS * S + rr];
            }
        }
    }
}

// ---------------------------------------------------------------------------
// K3: conv along D (4 segments) + fused SSIM + reduction.
// Block (h, n, seg); thread per w; sequential stream reads (3200B per step).
// ---------------------------------------------------------------------------
__global__ __launch_bounds__(S) void k3_dconv_ssim()
{
    const float GW[11] = GW_INIT;
    const int h   = blockIdx.x;
    const int n   = blockIdx.y;
    const int seg = blockIdx.z;
    const int d0  = seg * 40;
    const int w   = threadIdx.x;

    // element (d, c): base + d*LROW + c*S
    const float* __restrict__ base =
        g_bufB + (size_t)(n * S + h) * S * LROW + w;

    float w0[11], w1[11], w2[11], w3[11], w4[11];
    #pragma unroll
    for (int k = 0; k < 11; ++k) {
        const int dd = d0 - 5 + k;
        if (dd >= 0 && dd < S) {
            const float* p = base + (size_t)dd * LROW;
            w0[k] = p[0*S]; w1[k] = p[1*S]; w2[k] = p[2*S];
            w3[k] = p[3*S]; w4[k] = p[4*S];
        } else {
            w0[k] = 0.f; w1[k] = 0.f; w2[k] = 0.f; w3[k] = 0.f; w4[k] = 0.f;
        }
    }

    float lsum = 0.f;

    for (int ob = 0; ob < 44; ob += 11) {
        #pragma unroll
        for (int u = 0; u < 11; ++u) {
            const int o = ob + u;          // local output index, 0..43
            if (o < 40) {
                float mu1 = 0.f, mu2 = 0.f, xx = 0.f, yy = 0.f, xy = 0.f;
                #pragma unroll
                for (int k = 0; k < 11; ++k) {
                    const float g = GW[k];
                    mu1 += g * w0[k]; mu2 += g * w1[k];
                    xx  += g * w2[k]; yy  += g * w3[k];
                    xy  += g * w4[k];
                }
                const float mu1sq = mu1 * mu1;
                const float mu2sq = mu2 * mu2;
                const float mu12  = mu1 * mu2;
                const float s1  = xx - mu1sq;
                const float s2  = yy - mu2sq;
                const float s12 = xy - mu12;
                const float num = (2.f * mu12 + SSIM_C1) * (2.f * s12 + SSIM_C2);
                const float den = (mu1sq + mu2sq + SSIM_C1) * (s1 + s2 + SSIM_C2);
                lsum += __fdividef(num, den);
            }
            #pragma unroll
            for (int k = 0; k < 10; ++k) {
                w0[k] = w0[k+1]; w1[k] = w1[k+1]; w2[k] = w2[k+1];
                w3[k] = w3[k+1]; w4[k] = w4[k+1];
            }
            const int dd = d0 + o + 6;
            if (o < 39 && dd < S) {
                const float* p = base + (size_t)dd * LROW;
                w0[10] = p[0*S]; w1[10] = p[1*S]; w2[10] = p[2*S];
                w3[10] = p[3*S]; w4[10] = p[4*S];
            } else {
                w0[10] = 0.f; w1[10] = 0.f; w2[10] = 0.f; w3[10] = 0.f; w4[10] = 0.f;
            }
        }
    }

    // Block reduction (160 threads = 5 warps)
    #pragma unroll
    for (int t = 16; t > 0; t >>= 1)
        lsum += __shfl_xor_sync(0xffffffffu, lsum, t);
    __shared__ float red[5];
    const int wid = w >> 5, lane = w & 31;
    if (lane == 0) red[wid] = lsum;
    __syncthreads();
    if (w == 0) {
        const float bs = red[0] + red[1] + red[2] + red[3] + red[4];
        atomicAdd(&g_sum, (double)bs);
    }
}

__global__ void k4_finalize(float* __restrict__ out)
{
    out[0] = (float)(1.0 - g_sum / (double)NVOX);
}

// ---------------------------------------------------------------------------
extern "C" void kernel_launch(void* const* d_in, const int* in_sizes, int n_in,
                              void* d_out, int out_size)
{
    const float* img1 = (const float*)d_in[0];
    const float* img2 = (const float*)d_in[1];
    float* out = (float*)d_out;

    const int k12_smem = (2 * HROWS * S + 5 * HROWS * S) * (int)sizeof(float);
    // 112000 B: needs the opt-in attribute (idempotent, capture-safe)
    cudaFuncSetAttribute(k12_wh, cudaFuncAttributeMaxDynamicSharedMemorySize,
                         k12_smem);

    k0_init<<<1, 1>>>();
    k12_wh<<<dim3(NTILE, S, NB), 256, k12_smem>>>(img1, img2);
    k3_dconv_ssim<<<dim3(S, NB, 4), S>>>();
    k4_finalize<<<1, 1>>>(out);
}

// round 5
// speedup vs baseline: 1.6898x; 1.6898x over previous
#include <cuda_runtime.h>

// Problem geometry
#define S      160
#define NB     4
#define SLICE  (S * S)              // 25600
#define S3     (S * S * S)          // 4,096,000
#define NVOX   (NB * S3)            // 16,384,000
#define SSIM_C1 0.0001f
#define SSIM_C2 0.0009f

// H-tiling for fused W+H kernel
#define TH     30                   // outputs per block along h
#define HROWS  (TH + 10)            // 40 input rows incl. halo
#define NTILE  6                    // 6*30 = 180 >= 160 (last tile guarded)
#define PW     172                  // padded row width (5 zeros each side)

// Scratch after W+H conv. Layout [c][n][d][h][w] (R3 layout).
__device__ float g_bufB[5 * NVOX];
__device__ double g_sum;

// 11-tap Gaussian, sigma=1.5, normalized.
#define GW_INIT { 0.00102838f, 0.00759875f, 0.03600078f, 0.10936070f, \
                  0.21300554f, 0.26601172f, 0.21300554f, 0.10936070f, \
                  0.03600078f, 0.00759875f, 0.00102838f }

__global__ void k0_init() { g_sum = 0.0; }

// ---------------------------------------------------------------------------
// K12: fused products + W-conv + H-conv, thread-per-column, NO intermediate
// shared buffer. 160 threads (thread = w). Each thread reads its padded
// 11-value a/b window once per row (22 LDS), computes all 5 channel W-convs,
// pipes them through 5x11 h-shift registers, emits H outputs to bufB.
// One __syncthreads total.
// ---------------------------------------------------------------------------
extern __shared__ float s_raw[];

__device__ __forceinline__ void wconv5(
    const float* __restrict__ xr, const float* __restrict__ yr,
    const float* GW, float& A, float& B, float& AA, float& BB, float& AB)
{
    A = 0.f; B = 0.f; AA = 0.f; BB = 0.f; AB = 0.f;
    #pragma unroll
    for (int k = 0; k < 11; ++k) {
        const float a = xr[k];
        const float b = yr[k];
        const float g = GW[k];
        A  += g * a;
        B  += g * b;
        AA += g * (a * a);
        BB += g * (b * b);
        AB += g * (a * b);
    }
}

__global__ __launch_bounds__(160) void k12_wh(
    const float* __restrict__ x, const float* __restrict__ y)
{
    const float GW[11] = GW_INIT;
    float* xs = s_raw;                 // [HROWS][PW]
    float* ys = xs + HROWS * PW;       // [HROWS][PW]

    const int ht = blockIdx.x;
    const int d  = blockIdx.y;
    const int n  = blockIdx.z;
    const int h0 = ht * TH;
    const int tid = threadIdx.x;
    const size_t sbase = (size_t)n * S3 + (size_t)d * SLICE;

    // Load HROWS padded input rows (zeros at h and w edges), coalesced.
    for (int i = tid; i < HROWS * PW; i += 160) {
        const int r = i / PW, p = i - r * PW;
        const int hh = h0 - 5 + r;
        const int ww = p - 6;          // pad offset: col p holds w = p-6
        float a = 0.f, b = 0.f;
        if (hh >= 0 && hh < S && ww >= 0 && ww < S) {
            const size_t g = sbase + (size_t)hh * S + ww;
            a = x[g]; b = y[g];
        }
        xs[i] = a; ys[i] = b;
    }
    __syncthreads();

    const int w = tid;
    // window of W-conv values for rows (o..o+10); xs col index for center w
    // with taps k=0..10 -> padded col (w-5+k)+6 = w+1+k
    const int cbase = w + 1;

    float w0[11], w1[11], w2[11], w3[11], w4[11];
    #pragma unroll
    for (int k = 0; k < 11; ++k) {
        wconv5(xs + k * PW + cbase, ys + k * PW + cbase, GW,
               w0[k], w1[k], w2[k], w3[k], w4[k]);
    }

    #pragma unroll 2
    for (int o = 0; o < TH; ++o) {
        const int h = h0 + o;
        if (h < S) {
            float A = 0.f, B = 0.f, AA = 0.f, BB = 0.f, AB = 0.f;
            #pragma unroll
            for (int k = 0; k < 11; ++k) {
                const float g = GW[k];
                A  += g * w0[k]; B  += g * w1[k];
                AA += g * w2[k]; BB += g * w3[k];
                AB += g * w4[k];
            }
            float* dst = g_bufB + sbase + (size_t)h * S + w;
            dst[0]                = A;
            dst[(size_t)1 * NVOX] = B;
            dst[(size_t)2 * NVOX] = AA;
            dst[(size_t)3 * NVOX] = BB;
            dst[(size_t)4 * NVOX] = AB;
        }
        // shift and load next row's W-conv
        #pragma unroll
        for (int k = 0; k < 10; ++k) {
            w0[k] = w0[k+1]; w1[k] = w1[k+1]; w2[k] = w2[k+1];
            w3[k] = w3[k+1]; w4[k] = w4[k+1];
        }
        if (o + 11 < HROWS) {
            const int r = o + 11;
            wconv5(xs + r * PW + cbase, ys + r * PW + cbase, GW,
                   w0[10], w1[10], w2[10], w3[10], w4[10]);
        }
    }
}

// ---------------------------------------------------------------------------
// K3: conv along D (4 segments) + fused SSIM + reduction. (R3 version)
// ---------------------------------------------------------------------------
__global__ __launch_bounds__(S) void k3_dconv_ssim()
{
    const float GW[11] = GW_INIT;
    const int h   = blockIdx.x;
    const int n   = blockIdx.y;
    const int seg = blockIdx.z;
    const int d0  = seg * 40;
    const int w   = threadIdx.x;

    const size_t off = (size_t)n * S3 + (size_t)h * S + w;
    const float* __restrict__ p0 = g_bufB +                 off;
    const float* __restrict__ p1 = g_bufB + (size_t)1*NVOX + off;
    const float* __restrict__ p2 = g_bufB + (size_t)2*NVOX + off;
    const float* __restrict__ p3 = g_bufB + (size_t)3*NVOX + off;
    const float* __restrict__ p4 = g_bufB + (size_t)4*NVOX + off;

    float w0[11], w1[11], w2[11], w3[11], w4[11];
    #pragma unroll
    for (int k = 0; k < 11; ++k) {
        const int dd = d0 - 5 + k;
        if (dd >= 0 && dd < S) {
            const size_t ds = (size_t)dd * SLICE;
            w0[k] = p0[ds]; w1[k] = p1[ds]; w2[k] = p2[ds];
            w3[k] = p3[ds]; w4[k] = p4[ds];
        } else {
            w0[k] = 0.f; w1[k] = 0.f; w2[k] = 0.f; w3[k] = 0.f; w4[k] = 0.f;
        }
    }

    float lsum = 0.f;

    for (int ob = 0; ob < 44; ob += 11) {
        #pragma unroll
        for (int u = 0; u < 11; ++u) {
            const int o = ob + u;          // local output index, 0..43
            if (o < 40) {
                float mu1 = 0.f, mu2 = 0.f, xx = 0.f, yy = 0.f, xy = 0.f;
                #pragma unroll
                for (int k = 0; k < 11; ++k) {
                    const float g = GW[k];
                    mu1 += g * w0[k]; mu2 += g * w1[k];
                    xx  += g * w2[k]; yy  += g * w3[k];
                    xy  += g * w4[k];
                }
                const float mu1sq = mu1 * mu1;
                const float mu2sq = mu2 * mu2;
                const float mu12  = mu1 * mu2;
                const float s1  = xx - mu1sq;
                const float s2  = yy - mu2sq;
                const float s12 = xy - mu12;
                const float num = (2.f * mu12 + SSIM_C1) * (2.f * s12 + SSIM_C2);
                const float den = (mu1sq + mu2sq + SSIM_C1) * (s1 + s2 + SSIM_C2);
                lsum += __fdividef(num, den);
            }
            #pragma unroll
            for (int k = 0; k < 10; ++k) {
                w0[k] = w0[k+1]; w1[k] = w1[k+1]; w2[k] = w2[k+1];
                w3[k] = w3[k+1]; w4[k] = w4[k+1];
            }
            const int dd = d0 + o + 6;
            if (o < 39 && dd < S) {
                const size_t ds = (size_t)dd * SLICE;
                w0[10] = p0[ds]; w1[10] = p1[ds]; w2[10] = p2[ds];
                w3[10] = p3[ds]; w4[10] = p4[ds];
            } else {
                w0[10] = 0.f; w1[10] = 0.f; w2[10] = 0.f; w3[10] = 0.f; w4[10] = 0.f;
            }
        }
    }

    #pragma unroll
    for (int t = 16; t > 0; t >>= 1)
        lsum += __shfl_xor_sync(0xffffffffu, lsum, t);
    __shared__ float red[5];
    const int wid = w >> 5, lane = w & 31;
    if (lane == 0) red[wid] = lsum;
    __syncthreads();
    if (w == 0) {
        const float bs = red[0] + red[1] + red[2] + red[3] + red[4];
        atomicAdd(&g_sum, (double)bs);
    }
}

__global__ void k4_finalize(float* __restrict__ out)
{
    out[0] = (float)(1.0 - g_sum / (double)NVOX);
}

// ---------------------------------------------------------------------------
extern "C" void kernel_launch(void* const* d_in, const int* in_sizes, int n_in,
                              void* d_out, int out_size)
{
    const float* img1 = (const float*)d_in[0];
    const float* img2 = (const float*)d_in[1];
    float* out = (float*)d_out;

    const int k12_smem = 2 * HROWS * PW * (int)sizeof(float);   // 55040 B
    cudaFuncSetAttribute(k12_wh, cudaFuncAttributeMaxDynamicSharedMemorySize,
                         k12_smem);

    k0_init<<<1, 1>>>();
    k12_wh<<<dim3(NTILE, S, NB), 160, k12_smem>>>(img1, img2);
    k3_dconv_ssim<<<dim3(S, NB, 4), S>>>();
    k4_finalize<<<1, 1>>>(out);
}

// round 6
// speedup vs baseline: 2.2124x; 1.3092x over previous
#include <cuda_runtime.h>
#include <cuda_fp16.h>

// Problem geometry
#define S      160
#define NB     4
#define SLICE  (S * S)              // 25600
#define S3     (S * S * S)          // 4,096,000
#define NVOX   (NB * S3)            // 16,384,000
#define SSIM_C1 0.0001f
#define SSIM_C2 0.0009f

// H-tiling for fused W+H kernel
#define TH     30                   // outputs per block along h
#define HROWS  (TH + 10)            // 40 input rows incl. halo
#define NTILE  6                    // 6*30 = 180 >= 160 (last tile guarded)
#define PW     172                  // padded row width (5+160+7)

// K3 segmentation
#define DSEG   2
#define DLEN   (S / DSEG)           // 80
#define NPART  (S * NB * DSEG)      // 1280 partial sums

// Scratch after W+H conv, fp16 packed. Layout [n][d][h][w].
// P = (mu1pre, mu2pre), Q = (xx+yy, xy)
__device__ __half2 g_bufP[NVOX];
__device__ __half2 g_bufQ[NVOX];
__device__ float   g_part[NPART];

// 11-tap Gaussian, sigma=1.5, normalized.
#define GW_INIT { 0.00102838f, 0.00759875f, 0.03600078f, 0.10936070f, \
                  0.21300554f, 0.26601172f, 0.21300554f, 0.10936070f, \
                  0.03600078f, 0.00759875f, 0.00102838f }

// ---------------------------------------------------------------------------
// K12: fused products + W-conv + H-conv, thread-per-column, no intermediate
// buffer. 160 threads (thread = w). 4 channels: A=x, B=y, P=x^2+y^2, Q=xy.
// ---------------------------------------------------------------------------
extern __shared__ float s_raw[];

__device__ __forceinline__ void wconv4(
    const float* __restrict__ xr, const float* __restrict__ yr,
    const float* GW, float& A, float& B, float& P, float& Q)
{
    A = 0.f; B = 0.f; P = 0.f; Q = 0.f;
    #pragma unroll
    for (int k = 0; k < 11; ++k) {
        const float a = xr[k];
        const float b = yr[k];
        const float g = GW[k];
        A += g * a;
        B += g * b;
        P += g * fmaf(a, a, b * b);
        Q += g * (a * b);
    }
}

__global__ __launch_bounds__(160) void k12_wh(
    const float* __restrict__ x, const float* __restrict__ y)
{
    const float GW[11] = GW_INIT;
    float* xs = s_raw;                 // [HROWS][PW]
    float* ys = xs + HROWS * PW;       // [HROWS][PW]

    const int ht = blockIdx.x;
    const int d  = blockIdx.y;
    const int n  = blockIdx.z;
    const int h0 = ht * TH;
    const int tid = threadIdx.x;
    const size_t sbase = (size_t)n * S3 + (size_t)d * SLICE;

    // Load HROWS padded input rows (zeros at h and w edges), coalesced.
    for (int i = tid; i < HROWS * PW; i += 160) {
        const int r = i / PW, p = i - r * PW;
        const int hh = h0 - 5 + r;
        const int ww = p - 6;          // col p holds w = p-6
        float a = 0.f, b = 0.f;
        if (hh >= 0 && hh < S && ww >= 0 && ww < S) {
            const size_t g = sbase + (size_t)hh * S + ww;
            a = x[g]; b = y[g];
        }
        xs[i] = a; ys[i] = b;
    }
    __syncthreads();

    const int w = tid;
    const int cbase = w + 1;           // padded col of tap k: w+1+k

    float w0[11], w1[11], w2[11], w3[11];
    #pragma unroll
    for (int k = 0; k < 11; ++k)
        wconv4(xs + k * PW + cbase, ys + k * PW + cbase, GW,
               w0[k], w1[k], w2[k], w3[k]);

    #pragma unroll 2
    for (int o = 0; o < TH; ++o) {
        const int h = h0 + o;
        if (h < S) {
            float A = 0.f, B = 0.f, P = 0.f, Q = 0.f;
            #pragma unroll
            for (int k = 0; k < 11; ++k) {
                const float g = GW[k];
                A += g * w0[k]; B += g * w1[k];
                P += g * w2[k]; Q += g * w3[k];
            }
            const size_t o_idx = sbase + (size_t)h * S + w;
            g_bufP[o_idx] = __floats2half2_rn(A, B);
            g_bufQ[o_idx] = __floats2half2_rn(P, Q);
        }
        #pragma unroll
        for (int k = 0; k < 10; ++k) {
            w0[k] = w0[k+1]; w1[k] = w1[k+1];
            w2[k] = w2[k+1]; w3[k] = w3[k+1];
        }
        if (o + 11 < HROWS) {
            const int r = o + 11;
            wconv4(xs + r * PW + cbase, ys + r * PW + cbase, GW,
                   w0[10], w1[10], w2[10], w3[10]);
        }
    }
}

// ---------------------------------------------------------------------------
// K3: conv along D (2 segments of 80) + fused SSIM + block partial sums.
// Thread per w; two packed half2 streams, fp32 ring accumulators.
// ---------------------------------------------------------------------------
__global__ __launch_bounds__(S) void k3_dconv_ssim()
{
    const float GW[11] = GW_INIT;
    const int h   = blockIdx.x;
    const int n   = blockIdx.y;
    const int seg = blockIdx.z;
    const int d0  = seg * DLEN;
    const int w   = threadIdx.x;

    const size_t off = (size_t)n * S3 + (size_t)h * S + w;
    const __half2* __restrict__ pP = g_bufP + off;
    const __half2* __restrict__ pQ = g_bufQ + off;

    float w0[11], w1[11], w2[11], w3[11];
    #pragma unroll
    for (int k = 0; k < 11; ++k) {
        const int dd = d0 - 5 + k;
        if (dd >= 0 && dd < S) {
            const size_t ds = (size_t)dd * SLICE;
            const float2 vp = __half22float2(pP[ds]);
            const float2 vq = __half22float2(pQ[ds]);
            w0[k] = vp.x; w1[k] = vp.y; w2[k] = vq.x; w3[k] = vq.y;
        } else {
            w0[k] = 0.f; w1[k] = 0.f; w2[k] = 0.f; w3[k] = 0.f;
        }
    }

    float lsum = 0.f;

    for (int ob = 0; ob < 88; ob += 11) {
        #pragma unroll
        for (int u = 0; u < 11; ++u) {
            const int o = ob + u;          // local output index, 0..87
            if (o < DLEN) {
                float mu1 = 0.f, mu2 = 0.f, pp = 0.f, qq = 0.f;
                #pragma unroll
                for (int k = 0; k < 11; ++k) {
                    const float g = GW[k];
                    mu1 += g * w0[k]; mu2 += g * w1[k];
                    pp  += g * w2[k]; qq  += g * w3[k];
                }
                const float mu1sq = mu1 * mu1;
                const float mu2sq = mu2 * mu2;
                const float mu12  = mu1 * mu2;
                const float s1s2  = pp - mu1sq - mu2sq;   // sigma1^2 + sigma2^2
                const float s12   = qq - mu12;
                const float num = (2.f * mu12 + SSIM_C1) * (2.f * s12 + SSIM_C2);
                const float den = (mu1sq + mu2sq + SSIM_C1) * (s1s2 + SSIM_C2);
                lsum += __fdividef(num, den);
            }
            #pragma unroll
            for (int k = 0; k < 10; ++k) {
                w0[k] = w0[k+1]; w1[k] = w1[k+1];
                w2[k] = w2[k+1]; w3[k] = w3[k+1];
            }
            const int dd = d0 + o + 6;
            if (o < DLEN - 1 && dd < S) {
                const size_t ds = (size_t)dd * SLICE;
                const float2 vp = __half22float2(pP[ds]);
                const float2 vq = __half22float2(pQ[ds]);
                w0[10] = vp.x; w1[10] = vp.y; w2[10] = vq.x; w3[10] = vq.y;
            } else {
                w0[10] = 0.f; w1[10] = 0.f; w2[10] = 0.f; w3[10] = 0.f;
            }
        }
    }

    // Block reduction (160 threads = 5 warps) -> per-block partial
    #pragma unroll
    for (int t = 16; t > 0; t >>= 1)
        lsum += __shfl_xor_sync(0xffffffffu, lsum, t);
    __shared__ float red[5];
    const int wid = w >> 5, lane = w & 31;
    if (lane == 0) red[wid] = lsum;
    __syncthreads();
    if (w == 0) {
        const int b = blockIdx.x + S * (blockIdx.y + NB * blockIdx.z);
        g_part[b] = red[0] + red[1] + red[2] + red[3] + red[4];
    }
}

// ---------------------------------------------------------------------------
// K4: reduce 1280 partials -> scalar loss
// ---------------------------------------------------------------------------
__global__ __launch_bounds__(256) void k4_finalize(float* __restrict__ out)
{
    const int tid = threadIdx.x;
    float s = 0.f;
    for (int i = tid; i < NPART; i += 256) s += g_part[i];
    #pragma unroll
    for (int t = 16; t > 0; t >>= 1)
        s += __shfl_xor_sync(0xffffffffu, s, t);
    __shared__ float red[8];
    if ((tid & 31) == 0) red[tid >> 5] = s;
    __syncthreads();
    if (tid == 0) {
        float tot = 0.f;
        #pragma unroll
        for (int i = 0; i < 8; ++i) tot += red[i];
        out[0] = (float)(1.0 - (double)tot / (double)NVOX);
    }
}

// ---------------------------------------------------------------------------
extern "C" void kernel_launch(void* const* d_in, const int* in_sizes, int n_in,
                              void* d_out, int out_size)
{
    const float* img1 = (const float*)d_in[0];
    const float* img2 = (const float*)d_in[1];
    float* out = (float*)d_out;

    const int k12_smem = 2 * HROWS * PW * (int)sizeof(float);   // 55040 B
    cudaFuncSetAttribute(k12_wh, cudaFuncAttributeMaxDynamicSharedMemorySize,
                         k12_smem);

    k12_wh<<<dim3(NTILE, S, NB), 160, k12_smem>>>(img1, img2);
    k3_dconv_ssim<<<dim3(S, NB, DSEG), S>>>();
    k4_finalize<<<1, 256>>>(out);
}

// round 7
// speedup vs baseline: 2.2320x; 1.0089x over previous
#include <cuda_runtime.h>
#include <cuda_fp16.h>

// Problem geometry
#define S      160
#define NB     4
#define SLICE  (S * S)              // 25600
#define S3     (S * S * S)          // 4,096,000
#define NVOX   (NB * S3)            // 16,384,000
#define SSIM_C1 0.0001f
#define SSIM_C2 0.0009f

// H-tiling for fused W+H kernel (TH multiple of 11 -> shift regs rename away)
#define TH     33                   // outputs per block along h
#define HROWS  (TH + 10)            // 43 input rows incl. halo
#define NTILE  5                    // 5*33 = 165 >= 160 (last tile guarded)
#define PW     172                  // padded row width (>= 171)

// K3 segmentation
#define DSEG   2
#define DLEN   (S / DSEG)           // 80
#define NPART  (S * NB * DSEG)      // 1280 partial sums

// Scratch after W+H conv, fp16 packed. Layout [n][d][h][w].
// P = (mu1pre, mu2pre), Q = (xx+yy, xy)
__device__ __half2 g_bufP[NVOX];
__device__ __half2 g_bufQ[NVOX];
__device__ float   g_part[NPART];

// 11-tap Gaussian, sigma=1.5, normalized.
#define GW_INIT { 0.00102838f, 0.00759875f, 0.03600078f, 0.10936070f, \
                  0.21300554f, 0.26601172f, 0.21300554f, 0.10936070f, \
                  0.03600078f, 0.00759875f, 0.00102838f }

// ---------------------------------------------------------------------------
// K12: fused products + W-conv + H-conv, thread-per-column.
// (a,b) interleaved as float2 in smem -> 11 LDS.64 per row instead of 22 LDS.
// h-loop unrolled in blocks of 11 -> window shifts renamed, no MOVs.
// ---------------------------------------------------------------------------
extern __shared__ float2 s_xy[];     // [HROWS][PW]

__device__ __forceinline__ void wconv4(
    const float2* __restrict__ r, const float* GW,
    float& A, float& B, float& P, float& Q)
{
    A = 0.f; B = 0.f; P = 0.f; Q = 0.f;
    #pragma unroll
    for (int k = 0; k < 11; ++k) {
        const float2 v = r[k];
        const float g = GW[k];
        A += g * v.x;
        B += g * v.y;
        P += g * fmaf(v.x, v.x, v.y * v.y);
        Q += g * (v.x * v.y);
    }
}

__global__ __launch_bounds__(160) void k12_wh(
    const float* __restrict__ x, const float* __restrict__ y)
{
    const float GW[11] = GW_INIT;

    const int ht = blockIdx.x;
    const int d  = blockIdx.y;
    const int n  = blockIdx.z;
    const int h0 = ht * TH;
    const int tid = threadIdx.x;
    const size_t sbase = (size_t)n * S3 + (size_t)d * SLICE;

    // Load HROWS padded input rows (zeros at h and w edges), coalesced.
    for (int i = tid; i < HROWS * PW; i += 160) {
        const int r = i / PW, p = i - r * PW;
        const int hh = h0 - 5 + r;
        const int ww = p - 6;          // col p holds w = p-6
        float a = 0.f, b = 0.f;
        if (hh >= 0 && hh < S && ww >= 0 && ww < S) {
            const size_t g = sbase + (size_t)hh * S + ww;
            a = x[g]; b = y[g];
        }
        s_xy[i] = make_float2(a, b);
    }
    __syncthreads();

    const int w = tid;
    const int cbase = w + 1;           // padded col of tap k: w+1+k

    float w0[11], w1[11], w2[11], w3[11];
    #pragma unroll
    for (int k = 0; k < 11; ++k)
        wconv4(s_xy + k * PW + cbase, GW, w0[k], w1[k], w2[k], w3[k]);

    for (int ob = 0; ob < TH; ob += 11) {
        #pragma unroll
        for (int u = 0; u < 11; ++u) {
            const int o = ob + u;
            const int h = h0 + o;
            if (h < S) {
                float A = 0.f, B = 0.f, P = 0.f, Q = 0.f;
                #pragma unroll
                for (int k = 0; k < 11; ++k) {
                    const float g = GW[k];
                    A += g * w0[k]; B += g * w1[k];
                    P += g * w2[k]; Q += g * w3[k];
                }
                const size_t o_idx = sbase + (size_t)h * S + w;
                g_bufP[o_idx] = __floats2half2_rn(A, B);
                g_bufQ[o_idx] = __floats2half2_rn(P, Q);
            }
            #pragma unroll
            for (int k = 0; k < 10; ++k) {
                w0[k] = w0[k+1]; w1[k] = w1[k+1];
                w2[k] = w2[k+1]; w3[k] = w3[k+1];
            }
            if (o + 11 < HROWS)
                wconv4(s_xy + (o + 11) * PW + cbase, GW,
                       w0[10], w1[10], w2[10], w3[10]);
        }
    }
}

// ---------------------------------------------------------------------------
// K3: conv along D (2 segments of 80) + fused SSIM + block partial sums.
// ---------------------------------------------------------------------------
__global__ __launch_bounds__(S) void k3_dconv_ssim()
{
    const float GW[11] = GW_INIT;
    const int h   = blockIdx.x;
    const int n   = blockIdx.y;
    const int seg = blockIdx.z;
    const int d0  = seg * DLEN;
    const int w   = threadIdx.x;

    const size_t off = (size_t)n * S3 + (size_t)h * S + w;
    const __half2* __restrict__ pP = g_bufP + off;
    const __half2* __restrict__ pQ = g_bufQ + off;

    float w0[11], w1[11], w2[11], w3[11];
    #pragma unroll
    for (int k = 0; k < 11; ++k) {
        const int dd = d0 - 5 + k;
        if (dd >= 0 && dd < S) {
            const size_t ds = (size_t)dd * SLICE;
            const float2 vp = __half22float2(pP[ds]);
            const float2 vq = __half22float2(pQ[ds]);
            w0[k] = vp.x; w1[k] = vp.y; w2[k] = vq.x; w3[k] = vq.y;
        } else {
            w0[k] = 0.f; w1[k] = 0.f; w2[k] = 0.f; w3[k] = 0.f;
        }
    }

    float lsum = 0.f;

    for (int ob = 0; ob < 88; ob += 11) {
        #pragma unroll
        for (int u = 0; u < 11; ++u) {
            const int o = ob + u;          // local output index, 0..87
            if (o < DLEN) {
                float mu1 = 0.f, mu2 = 0.f, pp = 0.f, qq = 0.f;
                #pragma unroll
                for (int k = 0; k < 11; ++k) {
                    const float g = GW[k];
                    mu1 += g * w0[k]; mu2 += g * w1[k];
                    pp  += g * w2[k]; qq  += g * w3[k];
                }
                const float mu1sq = mu1 * mu1;
                const float mu2sq = mu2 * mu2;
                const float mu12  = mu1 * mu2;
                const float s1s2  = pp - mu1sq - mu2sq;
                const float s12   = qq - mu12;
                const float num = (2.f * mu12 + SSIM_C1) * (2.f * s12 + SSIM_C2);
                const float den = (mu1sq + mu2sq + SSIM_C1) * (s1s2 + SSIM_C2);
                lsum += __fdividef(num, den);
            }
            #pragma unroll
            for (int k = 0; k < 10; ++k) {
                w0[k] = w0[k+1]; w1[k] = w1[k+1];
                w2[k] = w2[k+1]; w3[k] = w3[k+1];
            }
            const int dd = d0 + o + 6;
            if (o < DLEN - 1 && dd < S) {
                const size_t ds = (size_t)dd * SLICE;
                const float2 vp = __half22float2(pP[ds]);
                const float2 vq = __half22float2(pQ[ds]);
                w0[10] = vp.x; w1[10] = vp.y; w2[10] = vq.x; w3[10] = vq.y;
            } else {
                w0[10] = 0.f; w1[10] = 0.f; w2[10] = 0.f; w3[10] = 0.f;
            }
        }
    }

    #pragma unroll
    for (int t = 16; t > 0; t >>= 1)
        lsum += __shfl_xor_sync(0xffffffffu, lsum, t);
    __shared__ float red[5];
    const int wid = w >> 5, lane = w & 31;
    if (lane == 0) red[wid] = lsum;
    __syncthreads();
    if (w == 0) {
        const int b = blockIdx.x + S * (blockIdx.y + NB * blockIdx.z);
        g_part[b] = red[0] + red[1] + red[2] + red[3] + red[4];
    }
}

// ---------------------------------------------------------------------------
// K4: reduce 1280 partials -> scalar loss
// ---------------------------------------------------------------------------
__global__ __launch_bounds__(256) void k4_finalize(float* __restrict__ out)
{
    const int tid = threadIdx.x;
    float s = 0.f;
    for (int i = tid; i < NPART; i += 256) s += g_part[i];
    #pragma unroll
    for (int t = 16; t > 0; t >>= 1)
        s += __shfl_xor_sync(0xffffffffu, s, t);
    __shared__ float red[8];
    if ((tid & 31) == 0) red[tid >> 5] = s;
    __syncthreads();
    if (tid == 0) {
        float tot = 0.f;
        #pragma unroll
        for (int i = 0; i < 8; ++i) tot += red[i];
        out[0] = (float)(1.0 - (double)tot / (double)NVOX);
    }
}

// ---------------------------------------------------------------------------
extern "C" void kernel_launch(void* const* d_in, const int* in_sizes, int n_in,
                              void* d_out, int out_size)
{
    const float* img1 = (const float*)d_in[0];
    const float* img2 = (const float*)d_in[1];
    float* out = (float*)d_out;

    const int k12_smem = HROWS * PW * (int)sizeof(float2);   // 59168 B
    cudaFuncSetAttribute(k12_wh, cudaFuncAttributeMaxDynamicSharedMemorySize,
                         k12_smem);

    k12_wh<<<dim3(NTILE, S, NB), 160, k12_smem>>>(img1, img2);
    k3_dconv_ssim<<<dim3(S, NB, DSEG), S>>>();
    k4_finalize<<<1, 256>>>(out);
}